// round 7
// baseline (speedup 1.0000x reference)
#include <cuda_runtime.h>

// SpikingCell recurrence, simplified (see R1):
//   clamp gate always-true -> dropped; spike counter unused -> dropped
//   per (b,n):  v += (refrac>=2) ? x[t-1] : 0 ; out=(v>=1); v-=out;
//               refrac = out ? 0 : refrac+1
// Pure streaming: 128MB in + 128MB out, zero reuse. DRAM mixed-R/W bound.
//
// Sweep so far: grain {1,2,4 floats/thread} x depth {8,16} all plateau at
// 38-41us / ~5.6TB/s; best = scalar @ 28 warps/SM (occupancy-capped by
// problem size). R7 targets the ~29% DRAM idle (R/W turnaround):
//   - stores of a batch deferred and issued back-to-back (burstier writes)
//   - __ldlu last-use loads: input lines invalidated after read, freeing L2
//     to buffer more of the write stream into larger writeback bursts.
// Geometry: proven optimum, 1024 blocks x 128 threads, ping-pong PF=8.

constexpr int B = 16, T = 256, N = 8192;
constexpr int THREADS = 128;
constexpr int GRID = (B * N) / THREADS;   // 1024 blocks, 6.92/SM
constexpr int PF = 8;                     // pipeline depth
constexpr int NBATCH = T / PF;            // 32 batches -> 16 ping-pong pairs

struct State { float v; int r; float d; };

__device__ __forceinline__ float stepf(State& s, float xnext)
{
    s.v += (s.r >= 2) ? s.d : 0.f;
    float o = (s.v >= 1.f) ? 1.f : 0.f;
    s.v -= o;
    s.r = (o != 0.f) ? 0 : (s.r + 1);
    s.d = xnext;
    return o;
}

__global__ __launch_bounds__(THREADS) void spiking_kernel(
    const float* __restrict__ x, float* __restrict__ out)
{
    int tid = blockIdx.x * THREADS + threadIdx.x;   // 0 .. B*N-1
    int b = tid >> 13;            // / N
    int n = tid & (N - 1);        // % N
    size_t base = (size_t)b * T * N + n;

    const float* __restrict__ xp = x + base;
    float* __restrict__ op = out + base;

    State s{0.f, 0, 0.f};

    float bufA[PF], bufB[PF], ob[PF];

    // prologue: fill A
#pragma unroll
    for (int i = 0; i < PF; i++) bufA[i] = __ldlu(xp + (size_t)i * N);
    xp += (size_t)PF * N;

#pragma unroll 1
    for (int pair = 0; pair < NBATCH / 2 - 1; pair++) {
        // loads for B up front, computes on A, then 8 back-to-back stores
#pragma unroll
        for (int i = 0; i < PF; i++) bufB[i] = __ldlu(xp + (size_t)i * N);
        xp += (size_t)PF * N;
#pragma unroll
        for (int i = 0; i < PF; i++) ob[i] = stepf(s, bufA[i]);
#pragma unroll
        for (int i = 0; i < PF; i++) __stcs(op + (size_t)i * N, ob[i]);
        op += (size_t)PF * N;

        // loads for A, computes on B, burst stores
#pragma unroll
        for (int i = 0; i < PF; i++) bufA[i] = __ldlu(xp + (size_t)i * N);
        xp += (size_t)PF * N;
#pragma unroll
        for (int i = 0; i < PF; i++) ob[i] = stepf(s, bufB[i]);
#pragma unroll
        for (int i = 0; i < PF; i++) __stcs(op + (size_t)i * N, ob[i]);
        op += (size_t)PF * N;
    }

    // tail: load final B, compute+store A, then compute+store B
#pragma unroll
    for (int i = 0; i < PF; i++) bufB[i] = __ldlu(xp + (size_t)i * N);
#pragma unroll
    for (int i = 0; i < PF; i++) ob[i] = stepf(s, bufA[i]);
#pragma unroll
    for (int i = 0; i < PF; i++) __stcs(op + (size_t)i * N, ob[i]);
    op += (size_t)PF * N;
#pragma unroll
    for (int i = 0; i < PF; i++) ob[i] = stepf(s, bufB[i]);
#pragma unroll
    for (int i = 0; i < PF; i++) __stcs(op + (size_t)i * N, ob[i]);
}

extern "C" void kernel_launch(void* const* d_in, const int* in_sizes, int n_in,
                              void* d_out, int out_size)
{
    const float* x = (const float*)d_in[0];
    float* out = (float*)d_out;
    spiking_kernel<<<GRID, THREADS>>>(x, out);
}